// round 4
// baseline (speedup 1.0000x reference)
#include <cuda_runtime.h>

#define N_NODES 16384
#define IN_DIM  512
#define OUT_DIM 256

// Scratch (device globals — no allocation allowed in kernel_launch)
__device__ float g_dinv[N_NODES];                 // 64 KB
__device__ float g_feat[(size_t)N_NODES * OUT_DIM]; // 16 MB: g = d ⊙ (xW^T + b)

// ---------------------------------------------------------------------------
// Kernel 1: d_inv_sqrt[i] = rsqrt(1 + sum_j A[i,j])
// One 256-thread block per row; float4 streaming loads.
// ---------------------------------------------------------------------------
__global__ void rowsum_kernel(const float* __restrict__ A) {
    const int row = blockIdx.x;
    const float4* a = reinterpret_cast<const float4*>(A + (size_t)row * N_NODES);
    float s = 0.f;
    for (int j = threadIdx.x; j < N_NODES / 4; j += blockDim.x) {
        float4 v = a[j];
        s += (v.x + v.y) + (v.z + v.w);
    }
    __shared__ float red[8];
    #pragma unroll
    for (int o = 16; o > 0; o >>= 1) s += __shfl_down_sync(0xffffffffu, s, o);
    if ((threadIdx.x & 31) == 0) red[threadIdx.x >> 5] = s;
    __syncthreads();
    if (threadIdx.x < 8) {
        s = red[threadIdx.x];
        #pragma unroll
        for (int o = 4; o > 0; o >>= 1) s += __shfl_down_sync(0xffu, s, o);
        if (threadIdx.x == 0) g_dinv[row] = rsqrtf(s + 1.0f);
    }
}

// ---------------------------------------------------------------------------
// Kernel 2: g[m,n] = d[m] * (sum_k x[m,k]*W[n,k] + b[n])
// BM=64, BN=64, BK=16, 256 threads, 4x4 accumulators.
// ---------------------------------------------------------------------------
__global__ void linear_kernel(const float* __restrict__ x,
                              const float* __restrict__ W,
                              const float* __restrict__ bias) {
    const int BM = 64, BN = 64, BK = 16;
    __shared__ float Xs[BK][BM + 4];
    __shared__ float Ws[BK][BN + 4];

    const int m0 = blockIdx.y * BM;
    const int n0 = blockIdx.x * BN;
    const int tid = threadIdx.x;
    const int tx = tid & 15;      // 0..15 (cols)
    const int ty = tid >> 4;      // 0..15 (rows)

    float acc[4][4] = {};

    const int lr = tid >> 2;            // 0..63 (tile row for loads)
    const int lc = (tid & 3) * 4;       // 0,4,8,12

    for (int kt = 0; kt < IN_DIM; kt += BK) {
        float4 v = *reinterpret_cast<const float4*>(x + (size_t)(m0 + lr) * IN_DIM + kt + lc);
        Xs[lc + 0][lr] = v.x; Xs[lc + 1][lr] = v.y;
        Xs[lc + 2][lr] = v.z; Xs[lc + 3][lr] = v.w;
        float4 w = *reinterpret_cast<const float4*>(W + (size_t)(n0 + lr) * IN_DIM + kt + lc);
        Ws[lc + 0][lr] = w.x; Ws[lc + 1][lr] = w.y;
        Ws[lc + 2][lr] = w.z; Ws[lc + 3][lr] = w.w;
        __syncthreads();

        #pragma unroll
        for (int k = 0; k < BK; k++) {
            float af[4], bf[4];
            #pragma unroll
            for (int i = 0; i < 4; i++) af[i] = Xs[k][ty * 4 + i];
            #pragma unroll
            for (int j = 0; j < 4; j++) bf[j] = Ws[k][tx * 4 + j];
            #pragma unroll
            for (int i = 0; i < 4; i++)
                #pragma unroll
                for (int j = 0; j < 4; j++)
                    acc[i][j] = fmaf(af[i], bf[j], acc[i][j]);
        }
        __syncthreads();
    }

    #pragma unroll
    for (int i = 0; i < 4; i++) {
        const int gm = m0 + ty * 4 + i;
        const float di = g_dinv[gm];
        #pragma unroll
        for (int j = 0; j < 4; j++) {
            const int gn = n0 + tx * 4 + j;
            g_feat[(size_t)gm * OUT_DIM + gn] = di * (acc[i][j] + bias[gn]);
        }
    }
}

// ---------------------------------------------------------------------------
// Kernel 3 (dominant): out[m,:] = d[m] * (sum_k A[m,k]*g[k,:] + g[m,:])
// BM=64, BN=256 (full width -> A read exactly once), BK=16,
// 256 threads (tx 0..31, ty 0..7), 8x8 accumulators, columns split as
// {tx*4 .. +3} and {128+tx*4 .. +3} for conflict-free LDS.128.
// ---------------------------------------------------------------------------
__global__ void __launch_bounds__(256, 2)
agg_kernel(const float* __restrict__ A, float* __restrict__ out) {
    const int BM = 64, BK = 16;
    __shared__ float As[BK][BM + 4];
    __shared__ float Bs[BK][OUT_DIM];

    const int m0 = blockIdx.x * BM;
    const int tid = threadIdx.x;
    const int tx = tid & 31;   // 0..31 (col groups)
    const int ty = tid >> 5;   // 0..7  (row groups of 8)

    float acc[8][8] = {};

    const int lr = tid >> 2;        // 0..63
    const int lc = (tid & 3) * 4;   // 0,4,8,12

    for (int kt = 0; kt < N_NODES; kt += BK) {
        // A tile: 64 rows x 16 cols, one float4 per thread, transposed store
        float4 v = *reinterpret_cast<const float4*>(A + (size_t)(m0 + lr) * N_NODES + kt + lc);
        As[lc + 0][lr] = v.x; As[lc + 1][lr] = v.y;
        As[lc + 2][lr] = v.z; As[lc + 3][lr] = v.w;

        // B tile: g rows kt..kt+15 x 256 cols = 1024 float4, 4 per thread
        #pragma unroll
        for (int t = 0; t < 4; t++) {
            const int idx = tid + t * 256;      // float4 index 0..1023
            const int br = idx >> 6;            // /64 -> row 0..15
            const int bc = (idx & 63) * 4;      // col
            *reinterpret_cast<float4*>(&Bs[br][bc]) =
                *reinterpret_cast<const float4*>(g_feat + (size_t)(kt + br) * OUT_DIM + bc);
        }
        __syncthreads();

        #pragma unroll
        for (int k = 0; k < BK; k++) {
            float af[8], bf[8];
            #pragma unroll
            for (int i = 0; i < 8; i++) af[i] = As[k][ty * 8 + i];
            float4 b0 = *reinterpret_cast<const float4*>(&Bs[k][tx * 4]);
            float4 b1 = *reinterpret_cast<const float4*>(&Bs[k][128 + tx * 4]);
            bf[0] = b0.x; bf[1] = b0.y; bf[2] = b0.z; bf[3] = b0.w;
            bf[4] = b1.x; bf[5] = b1.y; bf[6] = b1.z; bf[7] = b1.w;
            #pragma unroll
            for (int i = 0; i < 8; i++)
                #pragma unroll
                for (int j = 0; j < 8; j++)
                    acc[i][j] = fmaf(af[i], bf[j], acc[i][j]);
        }
        __syncthreads();
    }

    // Epilogue: add self-loop term g[m,:], scale by d[m]; float4 stores.
    #pragma unroll
    for (int i = 0; i < 8; i++) {
        const int gm = m0 + ty * 8 + i;
        const float di = g_dinv[gm];
        const size_t rowoff = (size_t)gm * OUT_DIM;
        {
            const int gn = tx * 4;
            float4 gv = *reinterpret_cast<const float4*>(g_feat + rowoff + gn);
            float4 o;
            o.x = di * (acc[i][0] + gv.x);
            o.y = di * (acc[i][1] + gv.y);
            o.z = di * (acc[i][2] + gv.z);
            o.w = di * (acc[i][3] + gv.w);
            *reinterpret_cast<float4*>(out + rowoff + gn) = o;
        }
        {
            const int gn = 128 + tx * 4;
            float4 gv = *reinterpret_cast<const float4*>(g_feat + rowoff + gn);
            float4 o;
            o.x = di * (acc[i][4] + gv.x);
            o.y = di * (acc[i][5] + gv.y);
            o.z = di * (acc[i][6] + gv.z);
            o.w = di * (acc[i][7] + gv.w);
            *reinterpret_cast<float4*>(out + rowoff + gn) = o;
        }
    }
}

// ---------------------------------------------------------------------------
extern "C" void kernel_launch(void* const* d_in, const int* in_sizes, int n_in,
                              void* d_out, int out_size) {
    const float* x  = (const float*)d_in[0];   // [16384, 512]
    const float* A  = (const float*)d_in[1];   // [16384, 16384]
    const float* W  = (const float*)d_in[2];   // [256, 512]
    const float* b  = (const float*)d_in[3];   // [256]
    float* out = (float*)d_out;                // [16384, 256]

    rowsum_kernel<<<N_NODES, 256>>>(A);
    linear_kernel<<<dim3(OUT_DIM / 64, N_NODES / 64), 256>>>(x, W, b);
    agg_kernel<<<N_NODES / 64, 256>>>(A, out);
}

// round 9
// speedup vs baseline: 2.1003x; 2.1003x over previous
#include <cuda_runtime.h>
#include <cstdint>

#define N_NODES 16384
#define IN_DIM  512
#define OUT_DIM 256

// ---------------------------------------------------------------------------
// Device scratch (no runtime allocation allowed)
// ---------------------------------------------------------------------------
__device__ float g_dinv[N_NODES];                         // 64 KB
__device__ float g_feat[(size_t)N_NODES * OUT_DIM];       // 16 MB: g (m-major, fp32) for self-loop
__device__ float g_gT[(size_t)OUT_DIM * N_NODES];         // 16 MB: g^T (n-major, tf32-rounded) = B operand

// ---------------------------------------------------------------------------
// Helpers
// ---------------------------------------------------------------------------
__device__ __forceinline__ unsigned smem_u32(const void* p) {
    unsigned r;
    asm("{ .reg .u64 t; cvta.to.shared.u64 t, %1; cvt.u32.u64 %0, t; }"
        : "=r"(r) : "l"(p));
    return r;
}

#define CP_ASYNC16(dst, src) \
    asm volatile("cp.async.cg.shared.global [%0], [%1], 16;\n" :: "r"(dst), "l"(src))
#define CP_COMMIT() asm volatile("cp.async.commit_group;\n" ::: "memory")
#define CP_WAIT1()  asm volatile("cp.async.wait_group 1;\n" ::: "memory")

__device__ __forceinline__ unsigned tf32_rna(float x) {
    unsigned r;
    asm("cvt.rna.tf32.f32 %0, %1;" : "=r"(r) : "f"(x));
    return r;
}

__device__ __forceinline__ void mma_tf32(float& d0, float& d1, float& d2, float& d3,
                                         unsigned a0, unsigned a1, unsigned a2, unsigned a3,
                                         unsigned b0, unsigned b1) {
    asm volatile(
        "mma.sync.aligned.m16n8k8.row.col.f32.tf32.tf32.f32 "
        "{%0,%1,%2,%3}, {%4,%5,%6,%7}, {%8,%9}, {%0,%1,%2,%3};\n"
        : "+f"(d0), "+f"(d1), "+f"(d2), "+f"(d3)
        : "r"(a0), "r"(a1), "r"(a2), "r"(a3), "r"(b0), "r"(b1));
}

// ---------------------------------------------------------------------------
// Kernel 1: d_inv_sqrt[i] = rsqrt(1 + sum_j A[i,j])   (at HBM roofline)
// ---------------------------------------------------------------------------
__global__ void rowsum_kernel(const float* __restrict__ A) {
    const int row = blockIdx.x;
    const float4* a = reinterpret_cast<const float4*>(A + (size_t)row * N_NODES);
    float s = 0.f;
    for (int j = threadIdx.x; j < N_NODES / 4; j += blockDim.x) {
        float4 v = a[j];
        s += (v.x + v.y) + (v.z + v.w);
    }
    __shared__ float red[8];
    #pragma unroll
    for (int o = 16; o > 0; o >>= 1) s += __shfl_down_sync(0xffffffffu, s, o);
    if ((threadIdx.x & 31) == 0) red[threadIdx.x >> 5] = s;
    __syncthreads();
    if (threadIdx.x < 8) {
        s = red[threadIdx.x];
        #pragma unroll
        for (int o = 4; o > 0; o >>= 1) s += __shfl_down_sync(0xffu, s, o);
        if (threadIdx.x == 0) g_dinv[row] = rsqrtf(s + 1.0f);
    }
}

// ---------------------------------------------------------------------------
// Kernel 2: g[m,n] = d[m]*(x[m,:]@W[n,:] + b[n])
// Writes g_feat (m-major fp32) and g_gT (n-major, tf32-RN-rounded).
// ---------------------------------------------------------------------------
__global__ void linear_kernel(const float* __restrict__ x,
                              const float* __restrict__ W,
                              const float* __restrict__ bias) {
    const int BM = 64, BN = 64, BK = 16;
    __shared__ float Xs[BK][BM + 4];
    __shared__ float Ws[BK][BN + 4];

    const int m0 = blockIdx.y * BM;
    const int n0 = blockIdx.x * BN;
    const int tid = threadIdx.x;
    const int tx = tid & 15;
    const int ty = tid >> 4;

    float acc[4][4] = {};

    const int lr = tid >> 2;
    const int lc = (tid & 3) * 4;

    for (int kt = 0; kt < IN_DIM; kt += BK) {
        float4 v = *reinterpret_cast<const float4*>(x + (size_t)(m0 + lr) * IN_DIM + kt + lc);
        Xs[lc + 0][lr] = v.x; Xs[lc + 1][lr] = v.y;
        Xs[lc + 2][lr] = v.z; Xs[lc + 3][lr] = v.w;
        float4 w = *reinterpret_cast<const float4*>(W + (size_t)(n0 + lr) * IN_DIM + kt + lc);
        Ws[lc + 0][lr] = w.x; Ws[lc + 1][lr] = w.y;
        Ws[lc + 2][lr] = w.z; Ws[lc + 3][lr] = w.w;
        __syncthreads();

        #pragma unroll
        for (int k = 0; k < BK; k++) {
            float af[4], bf[4];
            #pragma unroll
            for (int i = 0; i < 4; i++) af[i] = Xs[k][ty * 4 + i];
            #pragma unroll
            for (int j = 0; j < 4; j++) bf[j] = Ws[k][tx * 4 + j];
            #pragma unroll
            for (int i = 0; i < 4; i++)
                #pragma unroll
                for (int j = 0; j < 4; j++)
                    acc[i][j] = fmaf(af[i], bf[j], acc[i][j]);
        }
        __syncthreads();
    }

    float dv[4];
    #pragma unroll
    for (int i = 0; i < 4; i++) dv[i] = g_dinv[m0 + ty * 4 + i];

    // m-major fp32 rows (coalesced float4 per i)
    #pragma unroll
    for (int i = 0; i < 4; i++) {
        const int gm = m0 + ty * 4 + i;
        float4 o;
        o.x = dv[i] * (acc[i][0] + bias[n0 + tx * 4 + 0]);
        o.y = dv[i] * (acc[i][1] + bias[n0 + tx * 4 + 1]);
        o.z = dv[i] * (acc[i][2] + bias[n0 + tx * 4 + 2]);
        o.w = dv[i] * (acc[i][3] + bias[n0 + tx * 4 + 3]);
        *reinterpret_cast<float4*>(g_feat + (size_t)gm * OUT_DIM + n0 + tx * 4) = o;
    }
    // n-major tf32-rounded rows (uint4 per j: 4 contiguous k = gm)
    #pragma unroll
    for (int j = 0; j < 4; j++) {
        const int gn = n0 + tx * 4 + j;
        unsigned u[4];
        #pragma unroll
        for (int i = 0; i < 4; i++)
            u[i] = tf32_rna(dv[i] * (acc[i][j] + bias[gn]));
        uint4 o = make_uint4(u[0], u[1], u[2], u[3]);
        *reinterpret_cast<uint4*>(g_gT + (size_t)gn * N_NODES + m0 + ty * 4) = o;
    }
}

// ---------------------------------------------------------------------------
// Kernel 3: out[m,:] = d[m]*( A[m,:] @ g + g[m,:] )  via mma.sync tf32 (HMMA).
// CTA tile 128(M) x 256(N full width), BK=32, 512 threads = 16 warps (4x4),
// warp tile 32x64 = 2 m-tiles x 8 n-tiles of m16n8k8. 3-stage cp.async:
// chunk c lives in stage c%3 on BOTH the read and the prefetch side.
// SMEM rows padded to 36 floats => conflict-free fragment loads.
// ---------------------------------------------------------------------------
#define NC        (N_NODES / 32)          // 512 chunks
#define RS        36                      // padded row stride (floats)
#define A_FLOATS  (128 * RS)              // 4608
#define B_FLOATS  (256 * RS)              // 9216
#define STG_FL    (A_FLOATS + B_FLOATS)   // 13824 floats = 55296 B
#define AGG_SMEM  (3 * STG_FL * 4)        // 165888 B

__global__ void __launch_bounds__(512, 1)
agg_kernel(const float* __restrict__ A, float* __restrict__ out) {
    extern __shared__ float smf[];
    const int tid  = threadIdx.x;
    const int wid  = tid >> 5;
    const int lane = tid & 31;
    const int gid  = lane >> 2;     // 0..7
    const int tig  = lane & 3;      // 0..3
    const int wm   = wid & 3;       // warp row  (M blocks of 32)
    const int wn   = wid >> 2;      // warp col  (N blocks of 64)
    const int m0   = blockIdx.x * 128;

    // ---- cp.async geometry ----
    // A tile: 128 rows x 128 B. thread t: row t>>2, 32B quarter (t&3) = 2x16B.
    const int arow = tid >> 2;
    const int aoff = (tid & 3) * 32;           // byte offset within row
    const char* agp = reinterpret_cast<const char*>(A + (size_t)(m0 + arow) * N_NODES) + aoff;
    // B tile: 256 rows x 128 B. thread t: row t>>1, 64B half (t&1) = 4x16B.
    const int brow = tid >> 1;
    const int boff = (tid & 1) * 64;
    const char* bgp = reinterpret_cast<const char*>(g_gT + (size_t)brow * N_NODES) + boff;

    unsigned sA[3], sB[3];
    #pragma unroll
    for (int s = 0; s < 3; s++) {
        float* st = smf + s * STG_FL;
        sA[s] = smem_u32(st + arow * RS) + aoff;
        sB[s] = smem_u32(st + A_FLOATS + brow * RS) + boff;
    }

    // ---- prologue: prefetch chunks 0,1 into stages 0,1 ----
    #pragma unroll
    for (int p = 0; p < 2; p++) {
        #pragma unroll
        for (int i = 0; i < 2; i++) CP_ASYNC16(sA[p] + i * 16, agp + (size_t)p * 128 + i * 16);
        #pragma unroll
        for (int i = 0; i < 4; i++) CP_ASYNC16(sB[p] + i * 16, bgp + (size_t)p * 128 + i * 16);
        CP_COMMIT();
    }

    float d[2][8][4] = {};

    // ---- fragment base pointers (per stage) ----
    const float* aFB[3];
    const float* bFB[3];
    #pragma unroll
    for (int s = 0; s < 3; s++) {
        float* st = smf + s * STG_FL;
        aFB[s] = st + (wm * 32 + gid) * RS + tig;            // + mt*16*RS, +8*RS, +4, +k*8
        bFB[s] = st + A_FLOATS + (wn * 64 + gid) * RS + tig; // + nt*8*RS, +4, +k*8
    }

    for (int c = 0; c < NC; c++) {
        CP_WAIT1();                 // chunk c resident
        __syncthreads();

        const int s = c - (c / 3) * 3;   // c % 3  (read stage)
        const float* aF = aFB[s];
        const float* bF = bFB[s];

        #pragma unroll
        for (int ks = 0; ks < 4; ks++) {
            const int ko = ks * 8;
            unsigned a[2][4];
            #pragma unroll
            for (int mt = 0; mt < 2; mt++) {
                const float* ar = aF + mt * (16 * RS) + ko;
                a[mt][0] = tf32_rna(ar[0]);
                a[mt][1] = tf32_rna(ar[8 * RS]);
                a[mt][2] = tf32_rna(ar[4]);
                a[mt][3] = tf32_rna(ar[8 * RS + 4]);
            }
            #pragma unroll
            for (int nt = 0; nt < 8; nt++) {
                const float* br = bF + nt * (8 * RS) + ko;
                const unsigned b0 = __float_as_uint(br[0]);
                const unsigned b1 = __float_as_uint(br[4]);
                #pragma unroll
                for (int mt = 0; mt < 2; mt++)
                    mma_tf32(d[mt][nt][0], d[mt][nt][1], d[mt][nt][2], d[mt][nt][3],
                             a[mt][0], a[mt][1], a[mt][2], a[mt][3], b0, b1);
            }
        }
        __syncthreads();            // all warps done reading stage s

        const int cp = c + 2;
        if (cp < NC) {
            // FIX (R8 post-mortem): chunk cp goes into stage cp%3 — the stage
            // freed by chunk c-1 — NOT into the stage just consumed (c%3).
            const int sp = cp - (cp / 3) * 3;
            #pragma unroll
            for (int i = 0; i < 2; i++)
                CP_ASYNC16(sA[sp] + i * 16, agp + (size_t)cp * 128 + i * 16);
            #pragma unroll
            for (int i = 0; i < 4; i++)
                CP_ASYNC16(sB[sp] + i * 16, bgp + (size_t)cp * 128 + i * 16);
        }
        CP_COMMIT();                // empty group in tail keeps wait_group 1 exact
    }

    // ---- epilogue: out[m,n] = d[m]*(acc + g[m,n]) ----
    #pragma unroll
    for (int mt = 0; mt < 2; mt++) {
        const int mA = m0 + wm * 32 + mt * 16 + gid;   // rows mA and mA+8
        const float dm0 = g_dinv[mA];
        const float dm1 = g_dinv[mA + 8];
        const float* gf0 = g_feat + (size_t)mA * OUT_DIM;
        const float* gf1 = gf0 + (size_t)8 * OUT_DIM;
        float* op0 = out + (size_t)mA * OUT_DIM;
        float* op1 = op0 + (size_t)8 * OUT_DIM;
        #pragma unroll
        for (int nt = 0; nt < 8; nt++) {
            const int n = wn * 64 + nt * 8 + 2 * tig;
            float2 gv0 = *reinterpret_cast<const float2*>(gf0 + n);
            float2 gv1 = *reinterpret_cast<const float2*>(gf1 + n);
            float2 o0, o1;
            o0.x = dm0 * (d[mt][nt][0] + gv0.x);
            o0.y = dm0 * (d[mt][nt][1] + gv0.y);
            o1.x = dm1 * (d[mt][nt][2] + gv1.x);
            o1.y = dm1 * (d[mt][nt][3] + gv1.y);
            *reinterpret_cast<float2*>(op0 + n) = o0;
            *reinterpret_cast<float2*>(op1 + n) = o1;
        }
    }
}

// ---------------------------------------------------------------------------
extern "C" void kernel_launch(void* const* d_in, const int* in_sizes, int n_in,
                              void* d_out, int out_size) {
    const float* x = (const float*)d_in[0];   // [16384, 512]
    const float* A = (const float*)d_in[1];   // [16384, 16384]
    const float* W = (const float*)d_in[2];   // [256, 512]
    const float* b = (const float*)d_in[3];   // [256]
    float* out = (float*)d_out;               // [16384, 256]

    cudaFuncSetAttribute(agg_kernel, cudaFuncAttributeMaxDynamicSharedMemorySize, AGG_SMEM);

    rowsum_kernel<<<N_NODES, 256>>>(A);
    linear_kernel<<<dim3(OUT_DIM / 64, N_NODES / 64), 256>>>(x, W, b);
    agg_kernel<<<N_NODES / 128, 512, AGG_SMEM>>>(A, out);
}

// round 10
// speedup vs baseline: 2.1045x; 1.0020x over previous
#include <cuda_runtime.h>
#include <cstdint>

#define N_NODES 16384
#define IN_DIM  512
#define OUT_DIM 256

// ---------------------------------------------------------------------------
// Device scratch (no runtime allocation allowed)
// ---------------------------------------------------------------------------
__device__ float g_dinv[N_NODES];                         // 64 KB
__device__ float g_feat[(size_t)N_NODES * OUT_DIM];       // 16 MB: g (m-major, fp32) for self-loop
__device__ float g_gT[(size_t)OUT_DIM * N_NODES];         // 16 MB: g^T (n-major, tf32-rounded) = B operand

// ---------------------------------------------------------------------------
// Helpers
// ---------------------------------------------------------------------------
__device__ __forceinline__ unsigned smem_u32(const void* p) {
    unsigned r;
    asm("{ .reg .u64 t; cvta.to.shared.u64 t, %1; cvt.u32.u64 %0, t; }"
        : "=r"(r) : "l"(p));
    return r;
}

#define CP_ASYNC16(dst, src) \
    asm volatile("cp.async.cg.shared.global [%0], [%1], 16;\n" :: "r"(dst), "l"(src))
#define CP_COMMIT() asm volatile("cp.async.commit_group;\n" ::: "memory")
#define CP_WAIT1()  asm volatile("cp.async.wait_group 1;\n" ::: "memory")

__device__ __forceinline__ unsigned tf32_rna(float x) {
    unsigned r;
    asm("cvt.rna.tf32.f32 %0, %1;" : "=r"(r) : "f"(x));
    return r;
}

__device__ __forceinline__ void mma_tf32(float& d0, float& d1, float& d2, float& d3,
                                         unsigned a0, unsigned a1, unsigned a2, unsigned a3,
                                         unsigned b0, unsigned b1) {
    asm volatile(
        "mma.sync.aligned.m16n8k8.row.col.f32.tf32.tf32.f32 "
        "{%0,%1,%2,%3}, {%4,%5,%6,%7}, {%8,%9}, {%0,%1,%2,%3};\n"
        : "+f"(d0), "+f"(d1), "+f"(d2), "+f"(d3)
        : "r"(a0), "r"(a1), "r"(a2), "r"(a3), "r"(b0), "r"(b1));
}

// ---------------------------------------------------------------------------
// Kernel 1: d_inv_sqrt[i] = rsqrt(1 + sum_j A[i,j])   (at HBM roofline)
// ---------------------------------------------------------------------------
__global__ void rowsum_kernel(const float* __restrict__ A) {
    const int row = blockIdx.x;
    const float4* a = reinterpret_cast<const float4*>(A + (size_t)row * N_NODES);
    float s = 0.f;
    for (int j = threadIdx.x; j < N_NODES / 4; j += blockDim.x) {
        float4 v = a[j];
        s += (v.x + v.y) + (v.z + v.w);
    }
    __shared__ float red[8];
    #pragma unroll
    for (int o = 16; o > 0; o >>= 1) s += __shfl_down_sync(0xffffffffu, s, o);
    if ((threadIdx.x & 31) == 0) red[threadIdx.x >> 5] = s;
    __syncthreads();
    if (threadIdx.x < 8) {
        s = red[threadIdx.x];
        #pragma unroll
        for (int o = 4; o > 0; o >>= 1) s += __shfl_down_sync(0xffu, s, o);
        if (threadIdx.x == 0) g_dinv[row] = rsqrtf(s + 1.0f);
    }
}

// ---------------------------------------------------------------------------
// Kernel 2: g[m,n] = d[m]*(x[m,:]@W[n,:] + b[n])
// Writes g_feat (m-major fp32) and g_gT (n-major, tf32-RN-rounded).
// ---------------------------------------------------------------------------
__global__ void linear_kernel(const float* __restrict__ x,
                              const float* __restrict__ W,
                              const float* __restrict__ bias) {
    const int BM = 64, BN = 64, BK = 16;
    __shared__ float Xs[BK][BM + 4];
    __shared__ float Ws[BK][BN + 4];

    const int m0 = blockIdx.y * BM;
    const int n0 = blockIdx.x * BN;
    const int tid = threadIdx.x;
    const int tx = tid & 15;
    const int ty = tid >> 4;

    float acc[4][4] = {};

    const int lr = tid >> 2;
    const int lc = (tid & 3) * 4;

    for (int kt = 0; kt < IN_DIM; kt += BK) {
        float4 v = *reinterpret_cast<const float4*>(x + (size_t)(m0 + lr) * IN_DIM + kt + lc);
        Xs[lc + 0][lr] = v.x; Xs[lc + 1][lr] = v.y;
        Xs[lc + 2][lr] = v.z; Xs[lc + 3][lr] = v.w;
        float4 w = *reinterpret_cast<const float4*>(W + (size_t)(n0 + lr) * IN_DIM + kt + lc);
        Ws[lc + 0][lr] = w.x; Ws[lc + 1][lr] = w.y;
        Ws[lc + 2][lr] = w.z; Ws[lc + 3][lr] = w.w;
        __syncthreads();

        #pragma unroll
        for (int k = 0; k < BK; k++) {
            float af[4], bf[4];
            #pragma unroll
            for (int i = 0; i < 4; i++) af[i] = Xs[k][ty * 4 + i];
            #pragma unroll
            for (int j = 0; j < 4; j++) bf[j] = Ws[k][tx * 4 + j];
            #pragma unroll
            for (int i = 0; i < 4; i++)
                #pragma unroll
                for (int j = 0; j < 4; j++)
                    acc[i][j] = fmaf(af[i], bf[j], acc[i][j]);
        }
        __syncthreads();
    }

    float dv[4];
    #pragma unroll
    for (int i = 0; i < 4; i++) dv[i] = g_dinv[m0 + ty * 4 + i];

    // m-major fp32 rows (coalesced float4 per i)
    #pragma unroll
    for (int i = 0; i < 4; i++) {
        const int gm = m0 + ty * 4 + i;
        float4 o;
        o.x = dv[i] * (acc[i][0] + bias[n0 + tx * 4 + 0]);
        o.y = dv[i] * (acc[i][1] + bias[n0 + tx * 4 + 1]);
        o.z = dv[i] * (acc[i][2] + bias[n0 + tx * 4 + 2]);
        o.w = dv[i] * (acc[i][3] + bias[n0 + tx * 4 + 3]);
        *reinterpret_cast<float4*>(g_feat + (size_t)gm * OUT_DIM + n0 + tx * 4) = o;
    }
    // n-major tf32-rounded rows (uint4 per j: 4 contiguous k = gm)
    #pragma unroll
    for (int j = 0; j < 4; j++) {
        const int gn = n0 + tx * 4 + j;
        unsigned u[4];
        #pragma unroll
        for (int i = 0; i < 4; i++)
            u[i] = tf32_rna(dv[i] * (acc[i][j] + bias[gn]));
        uint4 o = make_uint4(u[0], u[1], u[2], u[3]);
        *reinterpret_cast<uint4*>(g_gT + (size_t)gn * N_NODES + m0 + ty * 4) = o;
    }
}

// ---------------------------------------------------------------------------
// Kernel 3: out[m,:] = d[m]*( A[m,:] @ g + g[m,:] )  via mma.sync tf32 (HMMA).
// CTA tile 128(M) x 256(N full width), BK=32, 512 threads = 16 warps (4x4),
// warp tile 32x64 = 2 m-tiles x 8 n-tiles of m16n8k8. 3-stage cp.async:
// chunk c lives in stage c%3 on BOTH the read and the prefetch side.
// SMEM rows padded to 36 floats => conflict-free fragment loads.
// ---------------------------------------------------------------------------
#define NC        (N_NODES / 32)          // 512 chunks
#define RS        36                      // padded row stride (floats)
#define A_FLOATS  (128 * RS)              // 4608
#define B_FLOATS  (256 * RS)              // 9216
#define STG_FL    (A_FLOATS + B_FLOATS)   // 13824 floats = 55296 B
#define AGG_SMEM  (3 * STG_FL * 4)        // 165888 B

__global__ void __launch_bounds__(512, 1)
agg_kernel(const float* __restrict__ A, float* __restrict__ out) {
    extern __shared__ float smf[];
    const int tid  = threadIdx.x;
    const int wid  = tid >> 5;
    const int lane = tid & 31;
    const int gid  = lane >> 2;     // 0..7
    const int tig  = lane & 3;      // 0..3
    const int wm   = wid & 3;       // warp row  (M blocks of 32)
    const int wn   = wid >> 2;      // warp col  (N blocks of 64)
    const int m0   = blockIdx.x * 128;

    // ---- cp.async geometry ----
    // A tile: 128 rows x 128 B. thread t: row t>>2, 32B quarter (t&3) = 2x16B.
    const int arow = tid >> 2;
    const int aoff = (tid & 3) * 32;           // byte offset within row
    const char* agp = reinterpret_cast<const char*>(A + (size_t)(m0 + arow) * N_NODES) + aoff;
    // B tile: 256 rows x 128 B. thread t: row t>>1, 64B half (t&1) = 4x16B.
    const int brow = tid >> 1;
    const int boff = (tid & 1) * 64;
    const char* bgp = reinterpret_cast<const char*>(g_gT + (size_t)brow * N_NODES) + boff;

    unsigned sA[3], sB[3];
    #pragma unroll
    for (int s = 0; s < 3; s++) {
        float* st = smf + s * STG_FL;
        sA[s] = smem_u32(st + arow * RS) + aoff;
        sB[s] = smem_u32(st + A_FLOATS + brow * RS) + boff;
    }

    // ---- prologue: prefetch chunks 0,1 into stages 0,1 ----
    #pragma unroll
    for (int p = 0; p < 2; p++) {
        #pragma unroll
        for (int i = 0; i < 2; i++) CP_ASYNC16(sA[p] + i * 16, agp + (size_t)p * 128 + i * 16);
        #pragma unroll
        for (int i = 0; i < 4; i++) CP_ASYNC16(sB[p] + i * 16, bgp + (size_t)p * 128 + i * 16);
        CP_COMMIT();
    }

    float d[2][8][4] = {};

    // ---- fragment base pointers (per stage) ----
    const float* aFB[3];
    const float* bFB[3];
    #pragma unroll
    for (int s = 0; s < 3; s++) {
        float* st = smf + s * STG_FL;
        aFB[s] = st + (wm * 32 + gid) * RS + tig;            // + mt*16*RS, +8*RS, +4, +k*8
        bFB[s] = st + A_FLOATS + (wn * 64 + gid) * RS + tig; // + nt*8*RS, +4, +k*8
    }

    for (int c = 0; c < NC; c++) {
        CP_WAIT1();                 // chunk c resident
        __syncthreads();

        const int s = c - (c / 3) * 3;   // c % 3  (read stage)
        const float* aF = aFB[s];
        const float* bF = bFB[s];

        #pragma unroll
        for (int ks = 0; ks < 4; ks++) {
            const int ko = ks * 8;
            unsigned a[2][4];
            #pragma unroll
            for (int mt = 0; mt < 2; mt++) {
                const float* ar = aF + mt * (16 * RS) + ko;
                a[mt][0] = tf32_rna(ar[0]);
                a[mt][1] = tf32_rna(ar[8 * RS]);
                a[mt][2] = tf32_rna(ar[4]);
                a[mt][3] = tf32_rna(ar[8 * RS + 4]);
            }
            #pragma unroll
            for (int nt = 0; nt < 8; nt++) {
                const float* br = bF + nt * (8 * RS) + ko;
                const unsigned b0 = __float_as_uint(br[0]);
                const unsigned b1 = __float_as_uint(br[4]);
                #pragma unroll
                for (int mt = 0; mt < 2; mt++)
                    mma_tf32(d[mt][nt][0], d[mt][nt][1], d[mt][nt][2], d[mt][nt][3],
                             a[mt][0], a[mt][1], a[mt][2], a[mt][3], b0, b1);
            }
        }
        __syncthreads();            // all warps done reading stage s

        const int cp = c + 2;
        if (cp < NC) {
            // FIX (R8 post-mortem): chunk cp goes into stage cp%3 — the stage
            // freed by chunk c-1 — NOT into the stage just consumed (c%3).
            const int sp = cp - (cp / 3) * 3;
            #pragma unroll
            for (int i = 0; i < 2; i++)
                CP_ASYNC16(sA[sp] + i * 16, agp + (size_t)cp * 128 + i * 16);
            #pragma unroll
            for (int i = 0; i < 4; i++)
                CP_ASYNC16(sB[sp] + i * 16, bgp + (size_t)cp * 128 + i * 16);
        }
        CP_COMMIT();                // empty group in tail keeps wait_group 1 exact
    }

    // ---- epilogue: out[m,n] = d[m]*(acc + g[m,n]) ----
    #pragma unroll
    for (int mt = 0; mt < 2; mt++) {
        const int mA = m0 + wm * 32 + mt * 16 + gid;   // rows mA and mA+8
        const float dm0 = g_dinv[mA];
        const float dm1 = g_dinv[mA + 8];
        const float* gf0 = g_feat + (size_t)mA * OUT_DIM;
        const float* gf1 = gf0 + (size_t)8 * OUT_DIM;
        float* op0 = out + (size_t)mA * OUT_DIM;
        float* op1 = op0 + (size_t)8 * OUT_DIM;
        #pragma unroll
        for (int nt = 0; nt < 8; nt++) {
            const int n = wn * 64 + nt * 8 + 2 * tig;
            float2 gv0 = *reinterpret_cast<const float2*>(gf0 + n);
            float2 gv1 = *reinterpret_cast<const float2*>(gf1 + n);
            float2 o0, o1;
            o0.x = dm0 * (d[mt][nt][0] + gv0.x);
            o0.y = dm0 * (d[mt][nt][1] + gv0.y);
            o1.x = dm1 * (d[mt][nt][2] + gv1.x);
            o1.y = dm1 * (d[mt][nt][3] + gv1.y);
            *reinterpret_cast<float2*>(op0 + n) = o0;
            *reinterpret_cast<float2*>(op1 + n) = o1;
        }
    }
}

// ---------------------------------------------------------------------------
extern "C" void kernel_launch(void* const* d_in, const int* in_sizes, int n_in,
                              void* d_out, int out_size) {
    const float* x = (const float*)d_in[0];   // [16384, 512]
    const float* A = (const float*)d_in[1];   // [16384, 16384]
    const float* W = (const float*)d_in[2];   // [256, 512]
    const float* b = (const float*)d_in[3];   // [256]
    float* out = (float*)d_out;               // [16384, 256]

    cudaFuncSetAttribute(agg_kernel, cudaFuncAttributeMaxDynamicSharedMemorySize, AGG_SMEM);

    rowsum_kernel<<<N_NODES, 256>>>(A);
    linear_kernel<<<dim3(OUT_DIM / 64, N_NODES / 64), 256>>>(x, W, b);
    agg_kernel<<<N_NODES / 128, 512, AGG_SMEM>>>(A, out);
}